// round 8
// baseline (speedup 1.0000x reference)
#include <cuda_runtime.h>
#include <cuda_bf16.h>
#include <cfloat>

#define KC 16
#define DC 64
#define NMAX 131072
#define CHUNK 256
#define NCHUNK_MAX (NMAX / CHUNK)

// ---------------- static device scratch ----------------
__device__ int   g_pred[NMAX];
__device__ int   g_ccx[NCHUNK_MAX * KC];
__device__ int   g_cct[NCHUNK_MAX * KC];
__device__ int   g_cbx[NCHUNK_MAX * KC];
__device__ int   g_cbt[NCHUNK_MAX * KC];
__device__ int   g_cntx[KC], g_cntt[KC], g_m[KC], g_off[KC], g_pow[KC];
__device__ float g_fill[KC];
__device__ float g_loss;
__device__ float g_bufx[2u * NMAX * DC];
__device__ float g_buft[2u * NMAX * DC];
__device__ unsigned g_scr[4u * NMAX * DC];   // overflow / XL key scratch

// sortable-uint encode with LSB reserved for source tag (<=1ulp perturbation)
__device__ __forceinline__ unsigned encKey(float f) {
    unsigned u = __float_as_uint(f);
    unsigned s = (u & 0x80000000u) ? ~u : (u | 0x80000000u);
    return s & ~1u;
}
__device__ __forceinline__ float decKey(unsigned key) {
    unsigned s = key & ~1u;
    unsigned u = (s & 0x80000000u) ? (s & 0x7fffffffu) : ~s;
    return __uint_as_float(u);
}

// ---------------- init ----------------
__global__ void initK() {
    int t = threadIdx.x;
    if (t < KC) g_fill[t] = 0.f;
    if (t == 0) g_loss = 0.f;
}

// ---------------- assignment + softmax filling + per-chunk counts (x AND t) ----------------
__global__ void assignK(const float* __restrict__ x, const float* __restrict__ C,
                        const int* __restrict__ pr, int N) {
    __shared__ float4 sC[KC * DC / 4];
    __shared__ float  sCC[KC];
    __shared__ float  sFill[KC];
    __shared__ int    sCnt[KC];
    __shared__ int    sCntT[KC];
    int tid = threadIdx.x;
    sC[tid] = ((const float4*)C)[tid];
    if (tid < KC) { sFill[tid] = 0.f; sCnt[tid] = 0; sCntT[tid] = 0; }
    __syncthreads();
    if (tid < KC) {
        float cc = 0.f;
        #pragma unroll
        for (int q = 0; q < DC / 4; q++) {
            float4 c = sC[tid * (DC / 4) + q];
            cc += c.x * c.x + c.y * c.y + c.z * c.z + c.w * c.w;
        }
        sCC[tid] = cc;
    }
    __syncthreads();

    int i = blockIdx.x * blockDim.x + tid;
    bool act = i < N;
    float sc[KC];
    int bk = 0;
    if (act) {
        atomicAdd(&sCntT[pr[i]], 1);
        float acc[KC];
        #pragma unroll
        for (int k = 0; k < KC; k++) acc[k] = 0.f;
        const float4* xr = (const float4*)(x + (size_t)i * DC);
        #pragma unroll
        for (int q = 0; q < DC / 4; q++) {
            float4 v = xr[q];
            #pragma unroll
            for (int k = 0; k < KC; k++) {
                float4 c = sC[k * (DC / 4) + q];
                acc[k] += v.x * c.x + v.y * c.y + v.z * c.z + v.w * c.w;
            }
        }
        float best = FLT_MAX;
        #pragma unroll
        for (int k = 0; k < KC; k++) {
            sc[k] = sCC[k] - 2.f * acc[k];
            if (sc[k] < best) { best = sc[k]; bk = k; }
        }
        g_pred[i] = bk;
        float sum = 0.f;
        #pragma unroll
        for (int k = 0; k < KC; k++) { float e = __expf(-4.f * (sc[k] - best)); sc[k] = e; sum += e; }
        float inv = 1.f / sum;
        #pragma unroll
        for (int k = 0; k < KC; k++) sc[k] *= inv;
        atomicAdd(&sCnt[bk], 1);
    } else {
        #pragma unroll
        for (int k = 0; k < KC; k++) sc[k] = 0.f;
    }
    int lane = tid & 31;
    #pragma unroll
    for (int k = 0; k < KC; k++) {
        float v = sc[k];
        v += __shfl_down_sync(0xffffffffu, v, 16);
        v += __shfl_down_sync(0xffffffffu, v, 8);
        v += __shfl_down_sync(0xffffffffu, v, 4);
        v += __shfl_down_sync(0xffffffffu, v, 2);
        v += __shfl_down_sync(0xffffffffu, v, 1);
        if (lane == 0) atomicAdd(&sFill[k], v);
    }
    __syncthreads();
    if (tid < KC) {
        g_ccx[blockIdx.x * KC + tid] = sCnt[tid];
        g_cct[blockIdx.x * KC + tid] = sCntT[tid];
        atomicAdd(&g_fill[tid], sFill[tid]);
    }
}

// ---------------- parallel chunk-base scan: one block per (src,k) ----------------
__global__ void scanAK(int nchunk) {
    int b = blockIdx.x;
    int k = b & 15;
    const int* cc = (b < 16) ? g_ccx : g_cct;
    int* cb       = (b < 16) ? g_cbx : g_cbt;
    __shared__ int wtmp[16];
    int tid = threadIdx.x, lane = tid & 31, wid = tid >> 5;
    int run = 0;
    for (int c0 = 0; c0 < nchunk; c0 += blockDim.x) {
        int c = c0 + tid;
        int v = (c < nchunk) ? cc[c * KC + k] : 0;
        int s = v;
        #pragma unroll
        for (int o = 1; o < 32; o <<= 1) {
            int y = __shfl_up_sync(0xffffffffu, s, o);
            if (lane >= o) s += y;
        }
        if (lane == 31) wtmp[wid] = s;
        __syncthreads();
        if (wid == 0) {
            int a = (lane < 16) ? wtmp[lane] : 0;
            #pragma unroll
            for (int o = 1; o < 16; o <<= 1) {
                int y = __shfl_up_sync(0xffffffffu, a, o);
                if (lane >= o) a += y;
            }
            if (lane < 16) wtmp[lane] = a;
        }
        __syncthreads();
        int base = (wid ? wtmp[wid - 1] : 0);
        int tot = wtmp[15];
        if (c < nchunk) cb[c * KC + k] = run + base + s - v;
        run += tot;
        __syncthreads();
    }
    if (tid == 0) { if (b < 16) g_cntx[k] = run; else g_cntt[k] = run; }
}

// ---------------- offsets ----------------
__global__ void scanBK() {
    if (threadIdx.x == 0) {
        int off = 0;
        for (int kk = 0; kk < KC; kk++) {
            int m = min(g_cntx[kk], g_cntt[kk]);
            g_m[kk] = m;
            int p = 1;
            while (p < m) p <<= 1;
            if (m == 0) p = 0;
            g_pow[kk] = p;
            g_off[kk] = off;
            off += p;
        }
    }
}

// ---------------- stable scatter into per-(cluster,dim) segments ----------------
__global__ void scatterK(const float* __restrict__ src, const int* __restrict__ predIn,
                         int isx, int N) {
    __shared__ int wcnt[8][KC];
    int tid = threadIdx.x;
    if (tid < 8 * KC) ((int*)wcnt)[tid] = 0;
    __syncthreads();
    const int* pred = isx ? g_pred : predIn;
    int i = blockIdx.x * blockDim.x + tid;
    int lane = tid & 31, w = tid >> 5;
    int k = 0, lr = 0;
    bool act = i < N;
    unsigned ball = __ballot_sync(0xffffffffu, act);
    if (act) {
        k = pred[i];
        unsigned mm = __match_any_sync(ball, k);
        lr = __popc(mm & ((1u << lane) - 1u));
        if (lane == (int)(__ffs(mm) - 1)) wcnt[w][k] = __popc(mm);
    }
    __syncthreads();
    if (act) {
        int base = isx ? g_cbx[blockIdx.x * KC + k] : g_cbt[blockIdx.x * KC + k];
        #pragma unroll
        for (int ww = 0; ww < 8; ww++)
            if (ww < w) base += wcnt[ww][k];
        int r = base + lr;
        int m = g_m[k];
        if (r < m) {
            int P = g_pow[k];
            float* buf = (isx ? g_bufx : g_buft) + (size_t)g_off[k] * DC + r;
            const float4* s4 = (const float4*)(src + (size_t)i * DC);
            #pragma unroll
            for (int q = 0; q < DC / 4; q++) {
                float4 v = s4[q];
                buf[(size_t)(4 * q + 0) * P] = v.x;
                buf[(size_t)(4 * q + 1) * P] = v.y;
                buf[(size_t)(4 * q + 2) * P] = v.z;
                buf[(size_t)(4 * q + 3) * P] = v.w;
            }
        }
    }
}

// ==================== bucket-level fast/slow W1 ====================

// in-place block exclusive scan over BT*PER entries; returns block total
template <int BT, int PER>
__device__ __forceinline__ int scanExInPlace(int* arr, int* wtmp) {
    constexpr int NW = BT / 32;
    int tid = threadIdx.x, lane = tid & 31, wid = tid >> 5;
    int v[PER];
    #pragma unroll
    for (int j = 0; j < PER; j++) v[j] = arr[tid * PER + j];
    int sum = 0;
    #pragma unroll
    for (int j = 0; j < PER; j++) { int t = v[j]; v[j] = sum; sum += t; }
    int inc = sum;
    #pragma unroll
    for (int o = 1; o < 32; o <<= 1) {
        int y = __shfl_up_sync(0xffffffffu, inc, o);
        if (lane >= o) inc += y;
    }
    if (lane == 31) wtmp[wid] = inc;
    __syncthreads();
    if (wid == 0) {
        int a = (lane < NW) ? wtmp[lane] : 0;
        #pragma unroll
        for (int o = 1; o < 32; o <<= 1) {
            int y = __shfl_up_sync(0xffffffffu, a, o);
            if (lane >= o) a += y;
        }
        if (lane < NW) wtmp[lane] = a;
    }
    __syncthreads();
    int base = (wid ? wtmp[wid - 1] : 0) + inc - sum;
    int total = wtmp[NW - 1];
    __syncthreads();
    #pragma unroll
    for (int j = 0; j < PER; j++) arr[tid * PER + j] = base + v[j];
    return total;
}

template <int BT>
__device__ __forceinline__ void blockReduceAdd(float acc, int m, float* redtmp) {
    constexpr int NW = BT / 32;
    int lane = threadIdx.x & 31, wid = threadIdx.x >> 5;
    #pragma unroll
    for (int o = 16; o; o >>= 1) acc += __shfl_down_sync(0xffffffffu, acc, o);
    if (lane == 0) redtmp[wid] = acc;
    __syncthreads();
    if (wid == 0) {
        float t = (lane < NW) ? redtmp[lane] : 0.f;
        #pragma unroll
        for (int o = 16; o; o >>= 1) t += __shfl_down_sync(0xffffffffu, t, o);
        if (lane == 0) atomicAdd(&g_loss, t / ((float)m * (float)DC));
    }
}

// PACKED tiers: hist[B] = cnt<<16 | nx  (valid while 2m <= 32768)
// Layout: hist[B] | run0[B] | S1[B] | keys[SLOTS]
template <int BT, int PER, int SLOTS, int LO, int HI>
__global__ void __launch_bounds__(BT) wassT() {
    constexpr int B = BT * PER;
    int seg = blockIdx.x;
    int k = seg >> 6, d = seg & 63;
    int m = g_m[k];
    int twoM = 2 * m;
    if (m <= 0 || twoM <= LO || twoM > HI) return;
    int P = g_pow[k];
    const float* bx = g_bufx + (size_t)g_off[k] * DC + (size_t)d * P;
    const float* bt = g_buft + (size_t)g_off[k] * DC + (size_t)d * P;

    extern __shared__ __align__(16) unsigned char smraw[];
    int* hist = (int*)smraw;
    int* run0 = hist + B;
    int* S1   = run0 + B;
    unsigned* skeys = (unsigned*)(S1 + B);
    __shared__ int   wtmp[32];
    __shared__ float redtmp[32];

    int tid = threadIdx.x;
    const float scale = (float)B / 12.f;

    for (int b = tid; b < B; b += BT) hist[b] = 0;
    __syncthreads();

    // phase 1: packed histogram
    for (int i = tid; i < twoM; i += BT) {
        unsigned key = (i < m) ? (encKey(bx[i]) | 1u) : encKey(bt[i - m]);
        float v = decKey(key);
        int b = min(max((int)((v + 6.f) * scale), 0), B - 1);
        atomicAdd((unsigned*)&hist[b], 0x10000u + (key & 1u));
    }
    __syncthreads();

    // signed per-bucket sums -> run0; scan to exclusive prefix
    for (int b = tid; b < B; b += BT) {
        int h = hist[b];
        run0[b] = 2 * (h & 0xffff) - (h >> 16);
    }
    __syncthreads();
    scanExInPlace<BT, PER>(run0, wtmp);
    __syncthreads();

    // slow-bucket compact offsets
    for (int b = tid; b < B; b += BT) {
        int cnt = hist[b] >> 16;
        int r0 = run0[b];
        S1[b] = (r0 <= cnt && r0 >= -cnt) ? cnt : 0;
    }
    __syncthreads();
    int S = scanExInPlace<BT, PER>(S1, wtmp);
    __syncthreads();

    unsigned* kbuf = (S <= SLOTS) ? skeys
                   : (g_scr + (size_t)g_off[k] * 2 * DC + (size_t)d * 2 * P);

    // phase 2: fast items emit directly; slow items scatter compactly
    float acc = 0.f;
    for (int i = tid; i < twoM; i += BT) {
        unsigned key = (i < m) ? (encKey(bx[i]) | 1u) : encKey(bt[i - m]);
        float v = decKey(key);
        int b = min(max((int)((v + 6.f) * scale), 0), B - 1);
        int cnt = hist[b] >> 16;
        int r0 = run0[b];
        float tv = (key & 1u) ? v : -v;
        if (r0 > cnt)       acc -= tv;
        else if (r0 < -cnt) acc += tv;
        else {
            int pos = atomicAdd(&S1[b], 1);
            kbuf[pos] = key;
        }
    }
    __syncthreads();

    // phase 3: resolve slow items (per-item, bucket recomputed from value)
    for (int idx = tid; idx < S; idx += BT) {
        unsigned kk = kbuf[idx];
        float v = decKey(kk);
        int b = min(max((int)((v + 6.f) * scale), 0), B - 1);
        int en = S1[b];
        int cnt = hist[b] >> 16;
        int st = en - cnt;
        int run = run0[b];
        int mytag = (kk & 1u) ? 1 : -1;
        for (int j = st; j < en; j++) {
            unsigned kj = kbuf[j];
            bool le = (kj < kk) || (kj == kk && j <= idx);
            if (le) run += (kj & 1u) ? 1 : -1;
        }
        acc += v * (fabsf((float)(run - mytag)) - fabsf((float)run));
    }
    __syncthreads();
    blockReduceAdd<BT>(acc, m, redtmp);
}

// XL tier: non-packed counts, global key buffer, any 2m > LO
template <int BT, int PER, int LO>
__global__ void __launch_bounds__(BT) wassXL() {
    constexpr int B = BT * PER;
    int seg = blockIdx.x;
    int k = seg >> 6, d = seg & 63;
    int m = g_m[k];
    int twoM = 2 * m;
    if (m <= 0 || twoM <= LO) return;
    int P = g_pow[k];
    const float* bx = g_bufx + (size_t)g_off[k] * DC + (size_t)d * P;
    const float* bt = g_buft + (size_t)g_off[k] * DC + (size_t)d * P;
    unsigned* kbuf = g_scr + (size_t)g_off[k] * 2 * DC + (size_t)d * 2 * P;

    extern __shared__ __align__(16) unsigned char smraw[];
    int* cntA = (int*)smraw;
    int* run0 = cntA + B;
    int* S1   = run0 + B;
    __shared__ int   wtmp[32];
    __shared__ float redtmp[32];

    int tid = threadIdx.x;
    const float scale = (float)B / 12.f;

    for (int b = tid; b < B; b += BT) { cntA[b] = 0; run0[b] = 0; }
    __syncthreads();

    for (int i = tid; i < twoM; i += BT) {
        unsigned key = (i < m) ? (encKey(bx[i]) | 1u) : encKey(bt[i - m]);
        float v = decKey(key);
        int b = min(max((int)((v + 6.f) * scale), 0), B - 1);
        atomicAdd(&cntA[b], 1);
        atomicAdd(&run0[b], (key & 1u) ? 1 : -1);
    }
    __syncthreads();
    scanExInPlace<BT, PER>(run0, wtmp);
    __syncthreads();

    for (int b = tid; b < B; b += BT) {
        int cnt = cntA[b];
        int r0 = run0[b];
        S1[b] = (r0 <= cnt && r0 >= -cnt) ? cnt : 0;
    }
    __syncthreads();
    int S = scanExInPlace<BT, PER>(S1, wtmp);
    __syncthreads();
    (void)S;

    float acc = 0.f;
    for (int i = tid; i < twoM; i += BT) {
        unsigned key = (i < m) ? (encKey(bx[i]) | 1u) : encKey(bt[i - m]);
        float v = decKey(key);
        int b = min(max((int)((v + 6.f) * scale), 0), B - 1);
        int cnt = cntA[b];
        int r0 = run0[b];
        float tv = (key & 1u) ? v : -v;
        if (r0 > cnt)       acc -= tv;
        else if (r0 < -cnt) acc += tv;
        else {
            int pos = atomicAdd(&S1[b], 1);
            kbuf[pos] = key;
        }
    }
    __syncthreads();

    for (int idx = tid; idx < S; idx += BT) {
        unsigned kk = kbuf[idx];
        float v = decKey(kk);
        int b = min(max((int)((v + 6.f) * scale), 0), B - 1);
        int en = S1[b];
        int cnt = cntA[b];
        int st = en - cnt;
        int run = run0[b];
        int mytag = (kk & 1u) ? 1 : -1;
        for (int j = st; j < en; j++) {
            unsigned kj = kbuf[j];
            bool le = (kj < kk) || (kj == kk && j <= idx);
            if (le) run += (kj & 1u) ? 1 : -1;
        }
        acc += v * (fabsf((float)(run - mytag)) - fabsf((float)run));
    }
    __syncthreads();
    blockReduceAdd<BT>(acc, m, redtmp);
}

// ---------------- finalize ----------------
__global__ void finalK(const float* __restrict__ ft, float* __restrict__ out, int N) {
    if (threadIdx.x == 0) {
        float lf = 0.f;
        for (int k = 0; k < KC; k++) {
            float df = g_fill[k] / (float)N - ft[k];
            lf += df * df;
        }
        out[0] = g_loss + lf / (float)KC;
    }
}

extern "C" void kernel_launch(void* const* d_in, const int* in_sizes, int n_in,
                              void* d_out, int out_size) {
    const float* x  = (const float*)d_in[0];
    const float* C  = (const float*)d_in[1];
    const float* ft = (const float*)d_in[2];
    const float* tg = (const float*)d_in[3];
    const int*   pr = (const int*)d_in[4];
    float* out = (float*)d_out;
    int N = in_sizes[0] / DC;
    int nblk = (N + CHUNK - 1) / CHUNK;

    // tier1: 2m<=8192:  BT=256, B=2048, SLOTS=4096  -> 40 KB
    // tier2: 2m<=16384: BT=512, B=4096, SLOTS=6144  -> 72 KB
    // tier3: 2m<=32768: BT=512, B=6144, SLOTS=8192  -> 104 KB
    // XL:    2m>32768:  BT=512, B=8192 (non-packed) -> 96 KB
    size_t s1 = (size_t)(3 * 2048 + 4096) * 4;
    size_t s2 = (size_t)(3 * 4096 + 6144) * 4;
    size_t s3 = (size_t)(3 * 6144 + 8192) * 4;
    size_t sx = (size_t)(3 * 8192) * 4;
    cudaFuncSetAttribute(wassT<256, 8, 4096, 0, 8192>,       cudaFuncAttributeMaxDynamicSharedMemorySize, (int)s1);
    cudaFuncSetAttribute(wassT<512, 8, 6144, 8192, 16384>,   cudaFuncAttributeMaxDynamicSharedMemorySize, (int)s2);
    cudaFuncSetAttribute(wassT<512, 12, 8192, 16384, 32768>, cudaFuncAttributeMaxDynamicSharedMemorySize, (int)s3);
    cudaFuncSetAttribute(wassXL<512, 16, 32768>,             cudaFuncAttributeMaxDynamicSharedMemorySize, (int)sx);

    initK<<<1, 32>>>();
    assignK<<<nblk, 256>>>(x, C, pr, N);
    scanAK<<<32, 512>>>(nblk);
    scanBK<<<1, 32>>>();
    scatterK<<<nblk, 256>>>(x, pr, 1, N);
    scatterK<<<nblk, 256>>>(tg, pr, 0, N);
    wassT<256, 8, 4096, 0, 8192>       <<<KC * DC, 256, s1>>>();
    wassT<512, 8, 6144, 8192, 16384>   <<<KC * DC, 512, s2>>>();
    wassT<512, 12, 8192, 16384, 32768> <<<KC * DC, 512, s3>>>();
    wassXL<512, 16, 32768>             <<<KC * DC, 512, sx>>>();
    finalK<<<1, 32>>>(ft, out, N);
}